// round 16
// baseline (speedup 1.0000x reference)
#include <cuda_runtime.h>
#include <cuda_fp16.h>
#include <cstdint>

#define BB 2
#define CC 128
#define NN 4096
#define NSS 2048
#define HH 4
#define DD 32

// device scratch (no cudaMalloc allowed)
__device__ float    g_X [BB*CC*NN];      // scattered input [b][c][n]
__device__ float    g_Qf[BB*CC*NN];      // Q fp32 [b][h*32+d][n], pre-scaled
__device__ uint32_t g_Kt[BB*CC*NN/2];    // K fp16 [b][h][n][dpair]  (transposed)
__device__ uint32_t g_Vb[BB*CC*NN/2];    // V fp16 [b][h*32+d][n] (n-pairs packed)
__device__ float    g_Op[BB*HH*2*NN*DD]; // split-K partial O [b][h][half][q][d]
__device__ float    g_Ls[BB*HH*2*NN];    // split-K partial lsum [b][h][half][q]

// ---------------------------------------------------------------------------
// PTX helpers
// ---------------------------------------------------------------------------
__device__ __forceinline__ uint32_t f2tf32(float x) {
    uint32_t u; asm("cvt.rna.tf32.f32 %0, %1;" : "=r"(u) : "f"(x)); return u;
}
__device__ __forceinline__ float tf32f(float x) {
    return __uint_as_float(f2tf32(x));
}
__device__ __forceinline__ uint32_t packh(float lo, float hi) {
    uint32_t u; asm("cvt.rn.f16x2.f32 %0, %1, %2;" : "=r"(u) : "f"(hi), "f"(lo)); return u;
}
__device__ __forceinline__ uint32_t ex2h(uint32_t x) {
    uint32_t y; asm("ex2.approx.f16x2 %0, %1;" : "=r"(y) : "r"(x)); return y;
}
__device__ __forceinline__ uint32_t hadd2(uint32_t a, uint32_t b) {
    uint32_t r; asm("add.f16x2 %0, %1, %2;" : "=r"(r) : "r"(a), "r"(b)); return r;
}
__device__ __forceinline__ uint32_t smem_u32p(const void* p) {
    uint32_t a;
    asm("{ .reg .u64 t; cvta.to.shared.u64 t, %1; cvt.u32.u64 %0, t; }" : "=r"(a) : "l"(p));
    return a;
}
__device__ __forceinline__ void ldsm_x4(uint32_t& r0, uint32_t& r1, uint32_t& r2,
                                        uint32_t& r3, uint32_t addr) {
    asm volatile("ldmatrix.sync.aligned.m8n8.x4.shared.b16 {%0,%1,%2,%3}, [%4];"
        : "=r"(r0), "=r"(r1), "=r"(r2), "=r"(r3) : "r"(addr));
}
__device__ __forceinline__ void mma_tf32_k8(float c[4], const uint32_t a[4],
                                            uint32_t b0, uint32_t b1) {
    asm volatile(
        "mma.sync.aligned.m16n8k8.row.col.f32.tf32.tf32.f32 "
        "{%0,%1,%2,%3}, {%4,%5,%6,%7}, {%8,%9}, {%0,%1,%2,%3};"
        : "+f"(c[0]), "+f"(c[1]), "+f"(c[2]), "+f"(c[3])
        : "r"(a[0]), "r"(a[1]), "r"(a[2]), "r"(a[3]), "r"(b0), "r"(b1));
}
__device__ __forceinline__ void mma_f16_k16(float c[4], const uint32_t a[4],
                                            uint32_t b0, uint32_t b1) {
    asm volatile(
        "mma.sync.aligned.m16n8k16.row.col.f32.f16.f16.f32 "
        "{%0,%1,%2,%3}, {%4,%5,%6,%7}, {%8,%9}, {%0,%1,%2,%3};"
        : "+f"(c[0]), "+f"(c[1]), "+f"(c[2]), "+f"(c[3])
        : "r"(a[0]), "r"(a[1]), "r"(a[2]), "r"(a[3]), "r"(b0), "r"(b1));
}

// ---------------------------------------------------------------------------
// prep: scatter points into g_X (R13 version: coalesced reads, scattered
// writes; 4 consecutive j per thread).
// ---------------------------------------------------------------------------
__global__ void prep_kernel(const float* __restrict__ sel, const float* __restrict__ drop,
                            const void* __restrict__ idx_sel, const void* __restrict__ idx_drop)
{
    int t = blockIdx.x * 256 + threadIdx.x;          // 0 .. BB*CC*NN/4-1
    int j4 = (t % (NN/4)) * 4;
    int c  = (t / (NN/4)) % CC;
    int b  = t / ((NN/4)*CC);
    const int* is = (const int*)idx_sel;
    bool is64 = (is[1] == 0) & (is[3] == 0) & (is[5] == 0) & (is[7] == 0);

    const float* src;
    const void*  idx;
    int jj;
    if (j4 < NSS) { src = sel;  idx = idx_sel;  jj = j4; }
    else          { src = drop; idx = idx_drop; jj = j4 - NSS; }

    float4 v = *(const float4*)&src[(b*CC + c)*NSS + jj];
    int c0, c1, c2, c3;
    if (is64) {
        const long long* ip = (const long long*)idx + b*NSS + jj;
        c0 = (int)ip[0]; c1 = (int)ip[1]; c2 = (int)ip[2]; c3 = (int)ip[3];
    } else {
        const int* ip = (const int*)idx + b*NSS + jj;
        c0 = ip[0]; c1 = ip[1]; c2 = ip[2]; c3 = ip[3];
    }
    float* dst = g_X + (size_t)(b*CC + c)*NN;
    dst[c0] = v.x; dst[c1] = v.y; dst[c2] = v.z; dst[c3] = v.w;
}

// ---------------------------------------------------------------------------
// projection (R13): Q,K,V single-pass tf32 (K fp16 transposed [n][dpair],
// V fp16 [d][npair]); skip split tf32. W chunks register-prefetched.
// ---------------------------------------------------------------------------
#define XST 68
#define WST 36
#define PSMEM (2*128*XST*4 + 2*128*WST*4)   // 106496 bytes

__global__ __launch_bounds__(256) void proj_kernel(
    const float* __restrict__ pcd_up,
    const float* __restrict__ Wq, const float* __restrict__ Wk,
    const float* __restrict__ Wv, const float* __restrict__ Wsk,
    float* __restrict__ out)
{
    extern __shared__ __align__(16) float psm[];
    float* Xh = psm;                 // [128][XST]
    float* Xl = psm + 128*XST;       // [128][XST]
    float* Wh = psm + 2*128*XST;     // [128][WST]
    float* Wl = Wh + 128*WST;        // [128][WST]

    int tid = threadIdx.x;
    int w = tid >> 5, lane = tid & 31, gid = lane >> 2, tig = lane & 3;
    int n0 = blockIdx.x * 64;
    int b  = blockIdx.y;
    int m0 = w * 16;

    int wm[4], wk4[4];
    #pragma unroll
    for (int r = 0; r < 4; r++) {
        int i = r*256 + tid;
        wm[r] = i >> 3; wk4[r] = (i & 7) << 2;
    }

    const float QSCALE = 0.17677669529663687f * 1.4426950408889634f;

    {
        const float* xs = g_X + b*CC*NN;
        #pragma unroll
        for (int i = tid; i < 2048; i += 256) {
            int r = i >> 4, c4 = (i & 15) << 2;
            float4 v = *(const float4*)&xs[r*NN + n0 + c4];
            Xh[r*XST + c4 + 0] = tf32f(v.x);
            Xh[r*XST + c4 + 1] = tf32f(v.y);
            Xh[r*XST + c4 + 2] = tf32f(v.z);
            Xh[r*XST + c4 + 3] = tf32f(v.w);
        }
    }

    for (int p = 0; p < 3; p++) {
        const float* Wp = (p == 0) ? Wq : (p == 1) ? Wk : Wv;
        float acc[8][4];
        #pragma unroll
        for (int i = 0; i < 8; i++)
            #pragma unroll
            for (int j = 0; j < 4; j++) acc[i][j] = 0.f;

        float4 wreg[4];
        #pragma unroll
        for (int r = 0; r < 4; r++)
            wreg[r] = *(const float4*)&Wp[wm[r]*CC + wk4[r]];

        for (int kc = 0; kc < 4; kc++) {
            __syncthreads();
            #pragma unroll
            for (int r = 0; r < 4; r++) {
                Wh[wm[r]*WST + wk4[r] + 0] = tf32f(wreg[r].x);
                Wh[wm[r]*WST + wk4[r] + 1] = tf32f(wreg[r].y);
                Wh[wm[r]*WST + wk4[r] + 2] = tf32f(wreg[r].z);
                Wh[wm[r]*WST + wk4[r] + 3] = tf32f(wreg[r].w);
            }
            __syncthreads();
            if (kc < 3) {
                #pragma unroll
                for (int r = 0; r < 4; r++)
                    wreg[r] = *(const float4*)&Wp[wm[r]*CC + (kc + 1)*32 + wk4[r]];
            }
            #pragma unroll
            for (int ks = 0; ks < 4; ks++) {
                int kk = ks * 8;
                uint32_t a[4];
                a[0] = __float_as_uint(Wh[(m0 + gid    )*WST + kk + tig    ]);
                a[1] = __float_as_uint(Wh[(m0 + gid + 8)*WST + kk + tig    ]);
                a[2] = __float_as_uint(Wh[(m0 + gid    )*WST + kk + tig + 4]);
                a[3] = __float_as_uint(Wh[(m0 + gid + 8)*WST + kk + tig + 4]);
                #pragma unroll
                for (int nt = 0; nt < 8; nt++) {
                    uint32_t b0 = __float_as_uint(Xh[(kc*32 + kk + tig    )*XST + nt*8 + gid]);
                    uint32_t b1 = __float_as_uint(Xh[(kc*32 + kk + tig + 4)*XST + nt*8 + gid]);
                    mma_tf32_k8(acc[nt], a, b0, b1);
                }
            }
        }
        if (p == 0) {
            float* q = g_Qf + (size_t)(b*CC)*NN;
            #pragma unroll
            for (int nt = 0; nt < 8; nt++) {
                int n = n0 + nt*8 + 2*tig;
                *(float2*)&q[(m0 + gid    )*NN + n] = make_float2(acc[nt][0]*QSCALE, acc[nt][1]*QSCALE);
                *(float2*)&q[(m0 + gid + 8)*NN + n] = make_float2(acc[nt][2]*QSCALE, acc[nt][3]*QSCALE);
            }
        } else if (p == 1) {
            __half* kt = (__half*)g_Kt;
            size_t kb = ((size_t)(b*HH + (w >> 1))) * NN;
            int dh = (w & 1)*16 + gid;
            #pragma unroll
            for (int nt = 0; nt < 8; nt++) {
                int n = n0 + nt*8 + 2*tig;
                kt[(kb + n    )*32 + dh    ] = __float2half(acc[nt][0]);
                kt[(kb + n + 1)*32 + dh    ] = __float2half(acc[nt][1]);
                kt[(kb + n    )*32 + dh + 8] = __float2half(acc[nt][2]);
                kt[(kb + n + 1)*32 + dh + 8] = __float2half(acc[nt][3]);
            }
        } else {
            uint32_t* dst = g_Vb + (size_t)(b*CC)*(NN/2);
            #pragma unroll
            for (int nt = 0; nt < 8; nt++) {
                int np = (n0 + nt*8) / 2 + tig;
                dst[(m0 + gid    )*(NN/2) + np] = packh(acc[nt][0], acc[nt][1]);
                dst[(m0 + gid + 8)*(NN/2) + np] = packh(acc[nt][2], acc[nt][3]);
            }
        }
    }

    // ---- skip pass: split tf32 (fp32-accurate), X from pcd_up ----
    __syncthreads();
    {
        const float* xs = pcd_up + b*CC*NN;
        #pragma unroll
        for (int i = tid; i < 2048; i += 256) {
            int r = i >> 4, c4 = (i & 15) << 2;
            float4 v = *(const float4*)&xs[r*NN + n0 + c4];
            float h0 = tf32f(v.x), h1 = tf32f(v.y), h2 = tf32f(v.z), h3 = tf32f(v.w);
            Xh[r*XST + c4 + 0] = h0;  Xl[r*XST + c4 + 0] = tf32f(v.x - h0);
            Xh[r*XST + c4 + 1] = h1;  Xl[r*XST + c4 + 1] = tf32f(v.y - h1);
            Xh[r*XST + c4 + 2] = h2;  Xl[r*XST + c4 + 2] = tf32f(v.z - h2);
            Xh[r*XST + c4 + 3] = h3;  Xl[r*XST + c4 + 3] = tf32f(v.w - h3);
        }
    }

    float acc[8][4];
    #pragma unroll
    for (int i = 0; i < 8; i++)
        #pragma unroll
        for (int j = 0; j < 4; j++) acc[i][j] = 0.f;

    float4 wreg[4];
    #pragma unroll
    for (int r = 0; r < 4; r++)
        wreg[r] = *(const float4*)&Wsk[wm[r]*CC + wk4[r]];

    for (int kc = 0; kc < 4; kc++) {
        __syncthreads();
        #pragma unroll
        for (int r = 0; r < 4; r++) {
            float h0 = tf32f(wreg[r].x), h1 = tf32f(wreg[r].y);
            float h2 = tf32f(wreg[r].z), h3 = tf32f(wreg[r].w);
            Wh[wm[r]*WST + wk4[r] + 0] = h0;  Wl[wm[r]*WST + wk4[r] + 0] = tf32f(wreg[r].x - h0);
            Wh[wm[r]*WST + wk4[r] + 1] = h1;  Wl[wm[r]*WST + wk4[r] + 1] = tf32f(wreg[r].y - h1);
            Wh[wm[r]*WST + wk4[r] + 2] = h2;  Wl[wm[r]*WST + wk4[r] + 2] = tf32f(wreg[r].z - h2);
            Wh[wm[r]*WST + wk4[r] + 3] = h3;  Wl[wm[r]*WST + wk4[r] + 3] = tf32f(wreg[r].w - h3);
        }
        __syncthreads();
        if (kc < 3) {
            #pragma unroll
            for (int r = 0; r < 4; r++)
                wreg[r] = *(const float4*)&Wsk[wm[r]*CC + (kc + 1)*32 + wk4[r]];
        }
        #pragma unroll
        for (int ks = 0; ks < 4; ks++) {
            int kk = ks * 8;
            uint32_t ah[4], al[4];
            ah[0] = __float_as_uint(Wh[(m0 + gid    )*WST + kk + tig    ]);
            ah[1] = __float_as_uint(Wh[(m0 + gid + 8)*WST + kk + tig    ]);
            ah[2] = __float_as_uint(Wh[(m0 + gid    )*WST + kk + tig + 4]);
            ah[3] = __float_as_uint(Wh[(m0 + gid + 8)*WST + kk + tig + 4]);
            al[0] = __float_as_uint(Wl[(m0 + gid    )*WST + kk + tig    ]);
            al[1] = __float_as_uint(Wl[(m0 + gid + 8)*WST + kk + tig    ]);
            al[2] = __float_as_uint(Wl[(m0 + gid    )*WST + kk + tig + 4]);
            al[3] = __float_as_uint(Wl[(m0 + gid + 8)*WST + kk + tig + 4]);
            #pragma unroll
            for (int nt = 0; nt < 8; nt++) {
                uint32_t bh0 = __float_as_uint(Xh[(kc*32 + kk + tig    )*XST + nt*8 + gid]);
                uint32_t bh1 = __float_as_uint(Xh[(kc*32 + kk + tig + 4)*XST + nt*8 + gid]);
                uint32_t bl0 = __float_as_uint(Xl[(kc*32 + kk + tig    )*XST + nt*8 + gid]);
                uint32_t bl1 = __float_as_uint(Xl[(kc*32 + kk + tig + 4)*XST + nt*8 + gid]);
                mma_tf32_k8(acc[nt], ah, bh0, bh1);
                mma_tf32_k8(acc[nt], ah, bl0, bl1);
                mma_tf32_k8(acc[nt], al, bh0, bh1);
            }
        }
    }
    #pragma unroll
    for (int nt = 0; nt < 8; nt++) {
        int n = n0 + nt*8 + 2*tig;
        float* o = out + (size_t)(b*CC)*NN;
        *(float2*)&o[(m0 + gid    )*NN + n] = make_float2(acc[nt][0], acc[nt][1]);
        *(float2*)&o[(m0 + gid + 8)*NN + n] = make_float2(acc[nt][2], acc[nt][3]);
    }
}

// ---------------------------------------------------------------------------
// flash attention SPLIT-K: each CTA handles 256 q x 2048 keys (half of N).
// fp16 m16n8k16, 256 threads, 8 warps x 2 M-subtiles (shared K/V fragments),
// merged S/PV per 16-key group (low register pressure), double-buffered smem,
// one barrier/kt, 2 CTAs/SM. Writes partial O and lsum; combiner finishes.
// ---------------------------------------------------------------------------
#define KPST 20
#define VPST 36
#define KBUF (64*KPST)
#define VBUF (32*VPST)

__global__ __launch_bounds__(256, 2) void flash_kernel()
{
    __shared__ __align__(16) uint32_t Kp[2*KBUF];    // [buf][key][dpair]
    __shared__ __align__(16) uint32_t Vp[2*VBUF];    // [buf][d][jpair]

    int tid = threadIdx.x;
    int w = tid >> 5, lane = tid & 31, gid = lane >> 2, tig = lane & 3;
    int qt = blockIdx.x >> 1, half = blockIdx.x & 1;
    int h = blockIdx.y, b = blockIdx.z;
    int q0 = qt * 256;

    const float*    Qf = g_Qf + (size_t)(b*CC + h*32)*NN + q0;
    const uint32_t* Kt = g_Kt + ((size_t)(b*HH + h)*NN + half*2048)*16;
    const uint32_t* Vu = g_Vb + (size_t)(b*CC + h*32)*(NN/2) + half*1024;

    // staging indices
    int skey = tid >> 2, sq = tid & 3;
    int svd  = tid >> 3, svq = tid & 7;

    // ldmatrix per-thread base addresses (buffer 0)
    int lrow = lane & 7, lm = lane >> 3;
    uint32_t kp_b = smem_u32p(Kp), vp_b = smem_u32p(Vp);
    uint32_t kaddr0 = kp_b + (uint32_t)(lrow*(KPST*4) + (lm >> 1)*32 + (lm & 1)*16);
    uint32_t vaddr0 = vp_b + (uint32_t)(((lm >> 1)*8 + lrow)*(VPST*4) + (lm & 1)*16);

    // Q fragments (fp16, persist all tiles): 2 subtiles of 16 rows
    uint32_t qa[2][2][4];
    #pragma unroll
    for (int st = 0; st < 2; st++) {
        int r0 = w*32 + st*16 + gid;
        #pragma unroll
        for (int ks = 0; ks < 2; ks++) {
            int d = ks*16 + 2*tig;
            qa[st][ks][0] = packh(Qf[(d    )*NN + r0    ], Qf[(d + 1)*NN + r0    ]);
            qa[st][ks][1] = packh(Qf[(d    )*NN + r0 + 8], Qf[(d + 1)*NN + r0 + 8]);
            qa[st][ks][2] = packh(Qf[(d + 8)*NN + r0    ], Qf[(d + 9)*NN + r0    ]);
            qa[st][ks][3] = packh(Qf[(d + 8)*NN + r0 + 8], Qf[(d + 9)*NN + r0 + 8]);
        }
    }

    float o[2][4][4];
    #pragma unroll
    for (int st = 0; st < 2; st++)
        #pragma unroll
        for (int i = 0; i < 4; i++)
            #pragma unroll
            for (int j = 0; j < 4; j++) o[st][i][j] = 0.f;
    float lsum[2][2] = {{0.f, 0.f}, {0.f, 0.f}};

    // stage tile 0 into buffer 0
    {
        uint4 kv = *(const uint4*)&Kt[(size_t)skey*16 + sq*4];
        uint4 vv = *(const uint4*)&Vu[(size_t)svd*(NN/2) + svq*4];
        *(uint4*)&Kp[skey*KPST + sq*4] = kv;
        *(uint4*)&Vp[svd*VPST + svq*4] = vv;
    }
    __syncthreads();

    for (int kt = 0; kt < 32; kt++) {
        int cur = kt & 1, nxt = cur ^ 1;
        uint32_t kaddr = kaddr0 + (uint32_t)(cur * (KBUF*4));
        uint32_t vaddr = vaddr0 + (uint32_t)(cur * (VBUF*4));

        uint4 nK, nV;
        if (kt < 31) {
            nK = *(const uint4*)&Kt[(size_t)((kt + 1)*64 + skey)*16 + sq*4];
            nV = *(const uint4*)&Vu[(size_t)svd*(NN/2) + (kt + 1)*32 + svq*4];
        }

        uint32_t hs[2][2] = {{0u, 0u}, {0u, 0u}};
        // merged S/PV per 16-key group: pa live only within group
        #pragma unroll
        for (int g = 0; g < 4; g++) {
            uint32_t pa[2][4];
            #pragma unroll
            for (int sub = 0; sub < 2; sub++) {
                int nt = 2*g + sub;
                uint32_t k0, k1, k2, k3;
                ldsm_x4(k0, k1, k2, k3, kaddr + (uint32_t)(nt*8*KPST*4));
                #pragma unroll
                for (int st = 0; st < 2; st++) {
                    float sv[4] = {0.f, 0.f, 0.f, 0.f};
                    mma_f16_k16(sv, qa[st][0], k0, k1);
                    mma_f16_k16(sv, qa[st][1], k2, k3);
                    uint32_t p01 = ex2h(packh(sv[0], sv[1]));
                    uint32_t p23 = ex2h(packh(sv[2], sv[3]));
                    hs[st][0] = hadd2(hs[st][0], p01);
                    hs[st][1] = hadd2(hs[st][1], p23);
                    pa[st][sub*2    ] = p01;
                    pa[st][sub*2 + 1] = p23;
                }
            }
            uint32_t vb0[4], vb1[4];
            ldsm_x4(vb0[0], vb0[1], vb0[2], vb0[3], vaddr + (uint32_t)(g*32));
            ldsm_x4(vb1[0], vb1[1], vb1[2], vb1[3], vaddr + (uint32_t)(16*VPST*4 + g*32));
            #pragma unroll
            for (int st = 0; st < 2; st++) {
                mma_f16_k16(o[st][0], pa[st], vb0[0], vb0[1]);
                mma_f16_k16(o[st][1], pa[st], vb0[2], vb0[3]);
                mma_f16_k16(o[st][2], pa[st], vb1[0], vb1[1]);
                mma_f16_k16(o[st][3], pa[st], vb1[2], vb1[3]);
            }
        }
        #pragma unroll
        for (int st = 0; st < 2; st++) {
            float2 t0 = __half22float2(*(const __half2*)&hs[st][0]);
            float2 t1 = __half22float2(*(const __half2*)&hs[st][1]);
            lsum[st][0] += t0.x + t0.y;
            lsum[st][1] += t1.x + t1.y;
        }

        if (kt < 31) {
            *(uint4*)&Kp[nxt*KBUF + skey*KPST + sq*4] = nK;
            *(uint4*)&Vp[nxt*VBUF + svd*VPST + svq*4] = nV;
            __syncthreads();
        }
    }

    // epilogue: write partial O [q][d] and lsum to scratch (no divide)
    float* Op = g_Op + (((size_t)(b*HH + h)*2 + half)*NN + q0)*32;
    float* Ls = g_Ls + ((size_t)(b*HH + h)*2 + half)*NN + q0;
    #pragma unroll
    for (int st = 0; st < 2; st++) {
        #pragma unroll
        for (int hf = 0; hf < 2; hf++) {
            lsum[st][hf] += __shfl_xor_sync(0xffffffffu, lsum[st][hf], 1);
            lsum[st][hf] += __shfl_xor_sync(0xffffffffu, lsum[st][hf], 2);
        }
        int r0 = w*32 + st*16 + gid;
        if (tig == 0) { Ls[r0] = lsum[st][0]; Ls[r0 + 8] = lsum[st][1]; }
        #pragma unroll
        for (int nt = 0; nt < 4; nt++) {
            int d = nt*8 + 2*tig;
            *(float2*)&Op[(r0    )*32 + d] = make_float2(o[st][nt][0], o[st][nt][1]);
            *(float2*)&Op[(r0 + 8)*32 + d] = make_float2(o[st][nt][2], o[st][nt][3]);
        }
    }
}

// ---------------------------------------------------------------------------
// combiner: out[c][n] += (O0 + O1)[q][d] / (l0 + l1), transposed via smem.
// grid (NN/64, HH, BB), 256 threads.
// ---------------------------------------------------------------------------
__global__ __launch_bounds__(256) void comb_kernel(float* __restrict__ out)
{
    __shared__ float T[64][33];
    int tid = threadIdx.x;
    int n0 = blockIdx.x * 64, h = blockIdx.y, b = blockIdx.z;

    size_t base = ((size_t)(b*HH + h)*2)*NN;
    const float* O0 = g_Op + (base      + n0)*32;
    const float* O1 = g_Op + (base + NN + n0)*32;
    const float* L0 = g_Ls + base      + n0;
    const float* L1 = g_Ls + base + NN + n0;

    int row = tid >> 2, dq = (tid & 3) * 8;
    float inv = 1.f / (L0[row] + L1[row]);
    #pragma unroll
    for (int u = 0; u < 2; u++) {
        float4 x = *(const float4*)&O0[row*32 + dq + u*4];
        float4 y = *(const float4*)&O1[row*32 + dq + u*4];
        T[row][dq + u*4 + 0] = (x.x + y.x) * inv;
        T[row][dq + u*4 + 1] = (x.y + y.y) * inv;
        T[row][dq + u*4 + 2] = (x.z + y.z) * inv;
        T[row][dq + u*4 + 3] = (x.w + y.w) * inv;
    }
    __syncthreads();

    int d = tid >> 3, nq = (tid & 7) * 8;
    float* orow = out + ((size_t)(b*CC) + h*32 + d)*NN + n0 + nq;
    #pragma unroll
    for (int u = 0; u < 2; u++) {
        float4 ov = *(float4*)&orow[u*4];
        ov.x += T[nq + u*4 + 0][d];
        ov.y += T[nq + u*4 + 1][d];
        ov.z += T[nq + u*4 + 2][d];
        ov.w += T[nq + u*4 + 3][d];
        *(float4*)&orow[u*4] = ov;
    }
}

extern "C" void kernel_launch(void* const* d_in, const int* in_sizes, int n_in,
                              void* d_out, int out_size)
{
    const float* pcd_up = (const float*)d_in[0];
    const float* sel    = (const float*)d_in[1];
    const float* drop   = (const float*)d_in[2];
    // d_in[3] = pcd_up_xyz, unused by the reference math
    const float* Wq     = (const float*)d_in[4];
    const float* Wk     = (const float*)d_in[5];
    const float* Wv     = (const float*)d_in[6];
    const float* Wsk    = (const float*)d_in[7];
    const void*  idxs   = d_in[8];
    const void*  idxd   = d_in[9];
    float* out = (float*)d_out;

    static bool attr_set = false;
    if (!attr_set) {
        cudaFuncSetAttribute(proj_kernel, cudaFuncAttributeMaxDynamicSharedMemorySize,
                             PSMEM);
        attr_set = true;
    }

    prep_kernel<<<(BB*CC*NN)/1024, 256>>>(sel, drop, idxs, idxd);
    proj_kernel<<<dim3(NN/64, BB), 256, PSMEM>>>(pcd_up, Wq, Wk, Wv, Wsk, out);
    flash_kernel<<<dim3(NN/256*2, HH, BB), 256>>>();
    comb_kernel<<<dim3(NN/64, HH, BB), 256>>>(out);
}

// round 17
// speedup vs baseline: 1.0057x; 1.0057x over previous
#include <cuda_runtime.h>
#include <cuda_fp16.h>
#include <cstdint>

#define BB 2
#define CC 128
#define NN 4096
#define NSS 2048
#define HH 4
#define DD 32

// device scratch (no cudaMalloc allowed)
__device__ float    g_X [BB*CC*NN];      // scattered input [b][c][n]
__device__ float    g_Qf[BB*CC*NN];      // Q fp32 [b][h*32+d][n], pre-scaled
__device__ uint32_t g_Kt[BB*CC*NN/2];    // K fp16 [b][h][n][dpair]  (transposed)
__device__ uint32_t g_Vb[BB*CC*NN/2];    // V fp16 [b][h*32+d][n] (n-pairs packed)

// ---------------------------------------------------------------------------
// PTX helpers
// ---------------------------------------------------------------------------
__device__ __forceinline__ uint32_t f2tf32(float x) {
    uint32_t u; asm("cvt.rna.tf32.f32 %0, %1;" : "=r"(u) : "f"(x)); return u;
}
__device__ __forceinline__ float tf32f(float x) {
    return __uint_as_float(f2tf32(x));
}
__device__ __forceinline__ uint32_t packh(float lo, float hi) {
    uint32_t u; asm("cvt.rn.f16x2.f32 %0, %1, %2;" : "=r"(u) : "f"(hi), "f"(lo)); return u;
}
__device__ __forceinline__ uint32_t ex2h(uint32_t x) {
    uint32_t y; asm("ex2.approx.f16x2 %0, %1;" : "=r"(y) : "r"(x)); return y;
}
__device__ __forceinline__ uint32_t hadd2(uint32_t a, uint32_t b) {
    uint32_t r; asm("add.f16x2 %0, %1, %2;" : "=r"(r) : "r"(a), "r"(b)); return r;
}
__device__ __forceinline__ uint32_t smem_u32p(const void* p) {
    uint32_t a;
    asm("{ .reg .u64 t; cvta.to.shared.u64 t, %1; cvt.u32.u64 %0, t; }" : "=r"(a) : "l"(p));
    return a;
}
__device__ __forceinline__ void ldsm_x4(uint32_t& r0, uint32_t& r1, uint32_t& r2,
                                        uint32_t& r3, uint32_t addr) {
    asm volatile("ldmatrix.sync.aligned.m8n8.x4.shared.b16 {%0,%1,%2,%3}, [%4];"
        : "=r"(r0), "=r"(r1), "=r"(r2), "=r"(r3) : "r"(addr));
}
__device__ __forceinline__ void mma_tf32_k8(float c[4], const uint32_t a[4],
                                            uint32_t b0, uint32_t b1) {
    asm volatile(
        "mma.sync.aligned.m16n8k8.row.col.f32.tf32.tf32.f32 "
        "{%0,%1,%2,%3}, {%4,%5,%6,%7}, {%8,%9}, {%0,%1,%2,%3};"
        : "+f"(c[0]), "+f"(c[1]), "+f"(c[2]), "+f"(c[3])
        : "r"(a[0]), "r"(a[1]), "r"(a[2]), "r"(a[3]), "r"(b0), "r"(b1));
}
// fp16-accumulate HMMA (2 f16x2 accumulator regs)
__device__ __forceinline__ void mma_f16_k16_h(uint32_t c[2], const uint32_t a[4],
                                              uint32_t b0, uint32_t b1) {
    asm volatile(
        "mma.sync.aligned.m16n8k16.row.col.f16.f16.f16.f16 "
        "{%0,%1}, {%2,%3,%4,%5}, {%6,%7}, {%0,%1};"
        : "+r"(c[0]), "+r"(c[1])
        : "r"(a[0]), "r"(a[1]), "r"(a[2]), "r"(a[3]), "r"(b0), "r"(b1));
}

// ---------------------------------------------------------------------------
// prep (R13): scatter points into g_X, 4 consecutive j per thread
// ---------------------------------------------------------------------------
__global__ void prep_kernel(const float* __restrict__ sel, const float* __restrict__ drop,
                            const void* __restrict__ idx_sel, const void* __restrict__ idx_drop)
{
    int t = blockIdx.x * 256 + threadIdx.x;
    int j4 = (t % (NN/4)) * 4;
    int c  = (t / (NN/4)) % CC;
    int b  = t / ((NN/4)*CC);
    const int* is = (const int*)idx_sel;
    bool is64 = (is[1] == 0) & (is[3] == 0) & (is[5] == 0) & (is[7] == 0);

    const float* src;
    const void*  idx;
    int jj;
    if (j4 < NSS) { src = sel;  idx = idx_sel;  jj = j4; }
    else          { src = drop; idx = idx_drop; jj = j4 - NSS; }

    float4 v = *(const float4*)&src[(b*CC + c)*NSS + jj];
    int c0, c1, c2, c3;
    if (is64) {
        const long long* ip = (const long long*)idx + b*NSS + jj;
        c0 = (int)ip[0]; c1 = (int)ip[1]; c2 = (int)ip[2]; c3 = (int)ip[3];
    } else {
        const int* ip = (const int*)idx + b*NSS + jj;
        c0 = ip[0]; c1 = ip[1]; c2 = ip[2]; c3 = ip[3];
    }
    float* dst = g_X + (size_t)(b*CC + c)*NN;
    dst[c0] = v.x; dst[c1] = v.y; dst[c2] = v.z; dst[c3] = v.w;
}

// ---------------------------------------------------------------------------
// projection (R13): Q,K,V single-pass tf32 (K fp16 transposed [n][dpair],
// V fp16 [d][npair]); skip split tf32. W chunks register-prefetched.
// ---------------------------------------------------------------------------
#define XST 68
#define WST 36
#define PSMEM (2*128*XST*4 + 2*128*WST*4)   // 106496 bytes

__global__ __launch_bounds__(256) void proj_kernel(
    const float* __restrict__ pcd_up,
    const float* __restrict__ Wq, const float* __restrict__ Wk,
    const float* __restrict__ Wv, const float* __restrict__ Wsk,
    float* __restrict__ out)
{
    extern __shared__ __align__(16) float psm[];
    float* Xh = psm;                 // [128][XST]
    float* Xl = psm + 128*XST;       // [128][XST]
    float* Wh = psm + 2*128*XST;     // [128][WST]
    float* Wl = Wh + 128*WST;        // [128][WST]

    int tid = threadIdx.x;
    int w = tid >> 5, lane = tid & 31, gid = lane >> 2, tig = lane & 3;
    int n0 = blockIdx.x * 64;
    int b  = blockIdx.y;
    int m0 = w * 16;

    int wm[4], wk4[4];
    #pragma unroll
    for (int r = 0; r < 4; r++) {
        int i = r*256 + tid;
        wm[r] = i >> 3; wk4[r] = (i & 7) << 2;
    }

    const float QSCALE = 0.17677669529663687f * 1.4426950408889634f;

    {
        const float* xs = g_X + b*CC*NN;
        #pragma unroll
        for (int i = tid; i < 2048; i += 256) {
            int r = i >> 4, c4 = (i & 15) << 2;
            float4 v = *(const float4*)&xs[r*NN + n0 + c4];
            Xh[r*XST + c4 + 0] = tf32f(v.x);
            Xh[r*XST + c4 + 1] = tf32f(v.y);
            Xh[r*XST + c4 + 2] = tf32f(v.z);
            Xh[r*XST + c4 + 3] = tf32f(v.w);
        }
    }

    for (int p = 0; p < 3; p++) {
        const float* Wp = (p == 0) ? Wq : (p == 1) ? Wk : Wv;
        float acc[8][4];
        #pragma unroll
        for (int i = 0; i < 8; i++)
            #pragma unroll
            for (int j = 0; j < 4; j++) acc[i][j] = 0.f;

        float4 wreg[4];
        #pragma unroll
        for (int r = 0; r < 4; r++)
            wreg[r] = *(const float4*)&Wp[wm[r]*CC + wk4[r]];

        for (int kc = 0; kc < 4; kc++) {
            __syncthreads();
            #pragma unroll
            for (int r = 0; r < 4; r++) {
                Wh[wm[r]*WST + wk4[r] + 0] = tf32f(wreg[r].x);
                Wh[wm[r]*WST + wk4[r] + 1] = tf32f(wreg[r].y);
                Wh[wm[r]*WST + wk4[r] + 2] = tf32f(wreg[r].z);
                Wh[wm[r]*WST + wk4[r] + 3] = tf32f(wreg[r].w);
            }
            __syncthreads();
            if (kc < 3) {
                #pragma unroll
                for (int r = 0; r < 4; r++)
                    wreg[r] = *(const float4*)&Wp[wm[r]*CC + (kc + 1)*32 + wk4[r]];
            }
            #pragma unroll
            for (int ks = 0; ks < 4; ks++) {
                int kk = ks * 8;
                uint32_t a[4];
                a[0] = __float_as_uint(Wh[(m0 + gid    )*WST + kk + tig    ]);
                a[1] = __float_as_uint(Wh[(m0 + gid + 8)*WST + kk + tig    ]);
                a[2] = __float_as_uint(Wh[(m0 + gid    )*WST + kk + tig + 4]);
                a[3] = __float_as_uint(Wh[(m0 + gid + 8)*WST + kk + tig + 4]);
                #pragma unroll
                for (int nt = 0; nt < 8; nt++) {
                    uint32_t b0 = __float_as_uint(Xh[(kc*32 + kk + tig    )*XST + nt*8 + gid]);
                    uint32_t b1 = __float_as_uint(Xh[(kc*32 + kk + tig + 4)*XST + nt*8 + gid]);
                    mma_tf32_k8(acc[nt], a, b0, b1);
                }
            }
        }
        if (p == 0) {
            float* q = g_Qf + (size_t)(b*CC)*NN;
            #pragma unroll
            for (int nt = 0; nt < 8; nt++) {
                int n = n0 + nt*8 + 2*tig;
                *(float2*)&q[(m0 + gid    )*NN + n] = make_float2(acc[nt][0]*QSCALE, acc[nt][1]*QSCALE);
                *(float2*)&q[(m0 + gid + 8)*NN + n] = make_float2(acc[nt][2]*QSCALE, acc[nt][3]*QSCALE);
            }
        } else if (p == 1) {
            __half* kt = (__half*)g_Kt;
            size_t kb = ((size_t)(b*HH + (w >> 1))) * NN;
            int dh = (w & 1)*16 + gid;
            #pragma unroll
            for (int nt = 0; nt < 8; nt++) {
                int n = n0 + nt*8 + 2*tig;
                kt[(kb + n    )*32 + dh    ] = __float2half(acc[nt][0]);
                kt[(kb + n + 1)*32 + dh    ] = __float2half(acc[nt][1]);
                kt[(kb + n    )*32 + dh + 8] = __float2half(acc[nt][2]);
                kt[(kb + n + 1)*32 + dh + 8] = __float2half(acc[nt][3]);
            }
        } else {
            uint32_t* dst = g_Vb + (size_t)(b*CC)*(NN/2);
            #pragma unroll
            for (int nt = 0; nt < 8; nt++) {
                int np = (n0 + nt*8) / 2 + tig;
                dst[(m0 + gid    )*(NN/2) + np] = packh(acc[nt][0], acc[nt][1]);
                dst[(m0 + gid + 8)*(NN/2) + np] = packh(acc[nt][2], acc[nt][3]);
            }
        }
    }

    // ---- skip pass: split tf32 (fp32-accurate), X from pcd_up ----
    __syncthreads();
    {
        const float* xs = pcd_up + b*CC*NN;
        #pragma unroll
        for (int i = tid; i < 2048; i += 256) {
            int r = i >> 4, c4 = (i & 15) << 2;
            float4 v = *(const float4*)&xs[r*NN + n0 + c4];
            float h0 = tf32f(v.x), h1 = tf32f(v.y), h2 = tf32f(v.z), h3 = tf32f(v.w);
            Xh[r*XST + c4 + 0] = h0;  Xl[r*XST + c4 + 0] = tf32f(v.x - h0);
            Xh[r*XST + c4 + 1] = h1;  Xl[r*XST + c4 + 1] = tf32f(v.y - h1);
            Xh[r*XST + c4 + 2] = h2;  Xl[r*XST + c4 + 2] = tf32f(v.z - h2);
            Xh[r*XST + c4 + 3] = h3;  Xl[r*XST + c4 + 3] = tf32f(v.w - h3);
        }
    }

    float acc[8][4];
    #pragma unroll
    for (int i = 0; i < 8; i++)
        #pragma unroll
        for (int j = 0; j < 4; j++) acc[i][j] = 0.f;

    float4 wreg[4];
    #pragma unroll
    for (int r = 0; r < 4; r++)
        wreg[r] = *(const float4*)&Wsk[wm[r]*CC + wk4[r]];

    for (int kc = 0; kc < 4; kc++) {
        __syncthreads();
        #pragma unroll
        for (int r = 0; r < 4; r++) {
            float h0 = tf32f(wreg[r].x), h1 = tf32f(wreg[r].y);
            float h2 = tf32f(wreg[r].z), h3 = tf32f(wreg[r].w);
            Wh[wm[r]*WST + wk4[r] + 0] = h0;  Wl[wm[r]*WST + wk4[r] + 0] = tf32f(wreg[r].x - h0);
            Wh[wm[r]*WST + wk4[r] + 1] = h1;  Wl[wm[r]*WST + wk4[r] + 1] = tf32f(wreg[r].y - h1);
            Wh[wm[r]*WST + wk4[r] + 2] = h2;  Wl[wm[r]*WST + wk4[r] + 2] = tf32f(wreg[r].z - h2);
            Wh[wm[r]*WST + wk4[r] + 3] = h3;  Wl[wm[r]*WST + wk4[r] + 3] = tf32f(wreg[r].w - h3);
        }
        __syncthreads();
        if (kc < 3) {
            #pragma unroll
            for (int r = 0; r < 4; r++)
                wreg[r] = *(const float4*)&Wsk[wm[r]*CC + (kc + 1)*32 + wk4[r]];
        }
        #pragma unroll
        for (int ks = 0; ks < 4; ks++) {
            int kk = ks * 8;
            uint32_t ah[4], al[4];
            ah[0] = __float_as_uint(Wh[(m0 + gid    )*WST + kk + tig    ]);
            ah[1] = __float_as_uint(Wh[(m0 + gid + 8)*WST + kk + tig    ]);
            ah[2] = __float_as_uint(Wh[(m0 + gid    )*WST + kk + tig + 4]);
            ah[3] = __float_as_uint(Wh[(m0 + gid + 8)*WST + kk + tig + 4]);
            al[0] = __float_as_uint(Wl[(m0 + gid    )*WST + kk + tig    ]);
            al[1] = __float_as_uint(Wl[(m0 + gid + 8)*WST + kk + tig    ]);
            al[2] = __float_as_uint(Wl[(m0 + gid    )*WST + kk + tig + 4]);
            al[3] = __float_as_uint(Wl[(m0 + gid + 8)*WST + kk + tig + 4]);
            #pragma unroll
            for (int nt = 0; nt < 8; nt++) {
                uint32_t bh0 = __float_as_uint(Xh[(kc*32 + kk + tig    )*XST + nt*8 + gid]);
                uint32_t bh1 = __float_as_uint(Xh[(kc*32 + kk + tig + 4)*XST + nt*8 + gid]);
                uint32_t bl0 = __float_as_uint(Xl[(kc*32 + kk + tig    )*XST + nt*8 + gid]);
                uint32_t bl1 = __float_as_uint(Xl[(kc*32 + kk + tig + 4)*XST + nt*8 + gid]);
                mma_tf32_k8(acc[nt], ah, bh0, bh1);
                mma_tf32_k8(acc[nt], ah, bl0, bl1);
                mma_tf32_k8(acc[nt], al, bh0, bh1);
            }
        }
    }
    #pragma unroll
    for (int nt = 0; nt < 8; nt++) {
        int n = n0 + nt*8 + 2*tig;
        float* o = out + (size_t)(b*CC)*NN;
        *(float2*)&o[(m0 + gid    )*NN + n] = make_float2(acc[nt][0], acc[nt][1]);
        *(float2*)&o[(m0 + gid + 8)*NN + n] = make_float2(acc[nt][2], acc[nt][3]);
    }
}

// ---------------------------------------------------------------------------
// flash attention (R13 structure + fp16-accumulate HMMA). 256 threads,
// 8 warps x 2 M-subtiles sharing K/V fragments, double-buffered smem,
// one barrier/kt. S accumulated in f16 (accumulator IS the ex2h input,
// no packh); PV accumulated in f16 per 64-key tile, folded to fp32 each kt.
// ---------------------------------------------------------------------------
#define KPST 20
#define VPST 36
#define KBUF (64*KPST)
#define VBUF (32*VPST)

__global__ __launch_bounds__(256, 1) void flash_kernel(float* __restrict__ out)
{
    __shared__ __align__(16) uint32_t Kp[2*KBUF];    // [buf][key][dpair]
    __shared__ __align__(16) uint32_t Vp[2*VBUF];    // [buf][d][jpair]

    int tid = threadIdx.x;
    int w = tid >> 5, lane = tid & 31, gid = lane >> 2, tig = lane & 3;
    int qt = blockIdx.x, h = blockIdx.y, b = blockIdx.z;
    int q0 = qt * 256;

    const float*    Qf = g_Qf + (size_t)(b*CC + h*32)*NN + q0;
    const uint32_t* Kt = g_Kt + ((size_t)(b*HH + h)*NN)*16;
    const uint32_t* Vu = g_Vb + (size_t)(b*CC + h*32)*(NN/2);

    int skey = tid >> 2, sq = tid & 3;
    int svd  = tid >> 3, svq = tid & 7;

    int lrow = lane & 7, lm = lane >> 3;
    uint32_t kp_b = smem_u32p(Kp), vp_b = smem_u32p(Vp);
    uint32_t kaddr0 = kp_b + (uint32_t)(lrow*(KPST*4) + (lm >> 1)*32 + (lm & 1)*16);
    uint32_t vaddr0 = vp_b + (uint32_t)(((lm >> 1)*8 + lrow)*(VPST*4) + (lm & 1)*16);

    // Q fragments (fp16, persist all tiles): 2 subtiles of 16 rows
    uint32_t qa[2][2][4];
    #pragma unroll
    for (int st = 0; st < 2; st++) {
        int r0 = w*32 + st*16 + gid;
        #pragma unroll
        for (int ks = 0; ks < 2; ks++) {
            int d = ks*16 + 2*tig;
            qa[st][ks][0] = packh(Qf[(d    )*NN + r0    ], Qf[(d + 1)*NN + r0    ]);
            qa[st][ks][1] = packh(Qf[(d    )*NN + r0 + 8], Qf[(d + 1)*NN + r0 + 8]);
            qa[st][ks][2] = packh(Qf[(d + 8)*NN + r0    ], Qf[(d + 9)*NN + r0    ]);
            qa[st][ks][3] = packh(Qf[(d + 8)*NN + r0 + 8], Qf[(d + 9)*NN + r0 + 8]);
        }
    }

    float o[2][4][4];
    #pragma unroll
    for (int st = 0; st < 2; st++)
        #pragma unroll
        for (int i = 0; i < 4; i++)
            #pragma unroll
            for (int j = 0; j < 4; j++) o[st][i][j] = 0.f;
    float lsum[2][2] = {{0.f, 0.f}, {0.f, 0.f}};

    // stage tile 0 into buffer 0
    {
        uint4 kv = *(const uint4*)&Kt[(size_t)skey*16 + sq*4];
        uint4 vv = *(const uint4*)&Vu[(size_t)svd*(NN/2) + svq*4];
        *(uint4*)&Kp[skey*KPST + sq*4] = kv;
        *(uint4*)&Vp[svd*VPST + svq*4] = vv;
    }
    __syncthreads();

    for (int kt = 0; kt < 64; kt++) {
        int cur = kt & 1, nxt = cur ^ 1;
        uint32_t kaddr = kaddr0 + (uint32_t)(cur * (KBUF*4));
        uint32_t vaddr = vaddr0 + (uint32_t)(cur * (VBUF*4));

        uint4 nK, nV;
        if (kt < 63) {
            nK = *(const uint4*)&Kt[(size_t)((kt + 1)*64 + skey)*16 + sq*4];
            nV = *(const uint4*)&Vu[(size_t)svd*(NN/2) + (kt + 1)*32 + svq*4];
        }

        // S = Q @ K^T (f16 accum; accumulator pair == ex2h input directly)
        uint32_t pa[2][4][4];
        uint32_t hs[2][2] = {{0u, 0u}, {0u, 0u}};
        #pragma unroll
        for (int nt = 0; nt < 8; nt++) {
            uint32_t k0, k1, k2, k3;
            ldsm_x4(k0, k1, k2, k3, kaddr + (uint32_t)(nt*8*KPST*4));
            #pragma unroll
            for (int st = 0; st < 2; st++) {
                uint32_t sc[2] = {0u, 0u};
                mma_f16_k16_h(sc, qa[st][0], k0, k1);
                mma_f16_k16_h(sc, qa[st][1], k2, k3);
                uint32_t p01 = ex2h(sc[0]);
                uint32_t p23 = ex2h(sc[1]);
                hs[st][0] = hadd2(hs[st][0], p01);
                hs[st][1] = hadd2(hs[st][1], p23);
                pa[st][nt >> 1][(nt & 1)*2    ] = p01;
                pa[st][nt >> 1][(nt & 1)*2 + 1] = p23;
            }
        }
        #pragma unroll
        for (int st = 0; st < 2; st++) {
            float2 t0 = __half22float2(*(const __half2*)&hs[st][0]);
            float2 t1 = __half22float2(*(const __half2*)&hs[st][1]);
            lsum[st][0] += t0.x + t0.y;
            lsum[st][1] += t1.x + t1.y;
        }

        // O_tile = P @ V in f16 accum (64-key partial), fold to fp32 after
        uint32_t oh[2][4][2];
        #pragma unroll
        for (int st = 0; st < 2; st++)
            #pragma unroll
            for (int nt = 0; nt < 4; nt++) { oh[st][nt][0] = 0u; oh[st][nt][1] = 0u; }

        #pragma unroll
        for (int g = 0; g < 4; g++) {
            uint32_t vb0[4], vb1[4];
            ldsm_x4(vb0[0], vb0[1], vb0[2], vb0[3], vaddr + (uint32_t)(g*32));
            ldsm_x4(vb1[0], vb1[1], vb1[2], vb1[3], vaddr + (uint32_t)(16*VPST*4 + g*32));
            #pragma unroll
            for (int st = 0; st < 2; st++) {
                mma_f16_k16_h(oh[st][0], pa[st][g], vb0[0], vb0[1]);
                mma_f16_k16_h(oh[st][1], pa[st][g], vb0[2], vb0[3]);
                mma_f16_k16_h(oh[st][2], pa[st][g], vb1[0], vb1[1]);
                mma_f16_k16_h(oh[st][3], pa[st][g], vb1[2], vb1[3]);
            }
        }
        // fold f16 tile partials into fp32 accumulators
        #pragma unroll
        for (int st = 0; st < 2; st++)
            #pragma unroll
            for (int nt = 0; nt < 4; nt++) {
                float2 u0 = __half22float2(*(const __half2*)&oh[st][nt][0]);
                float2 u1 = __half22float2(*(const __half2*)&oh[st][nt][1]);
                o[st][nt][0] += u0.x;
                o[st][nt][1] += u0.y;
                o[st][nt][2] += u1.x;
                o[st][nt][3] += u1.y;
            }

        if (kt < 63) {
            *(uint4*)&Kp[nxt*KBUF + skey*KPST + sq*4] = nK;
            *(uint4*)&Vp[nxt*VBUF + svd*VPST + svq*4] = nV;
            __syncthreads();
        }
    }

    // epilogue: reduce lsum across row group, divide, add into out
    #pragma unroll
    for (int st = 0; st < 2; st++) {
        #pragma unroll
        for (int half = 0; half < 2; half++) {
            lsum[st][half] += __shfl_xor_sync(0xffffffffu, lsum[st][half], 1);
            lsum[st][half] += __shfl_xor_sync(0xffffffffu, lsum[st][half], 2);
        }
    }
    #pragma unroll
    for (int st = 0; st < 2; st++) {
        int r0 = w*32 + st*16 + gid;
        float inv0 = 1.f / lsum[st][0], inv1 = 1.f / lsum[st][1];
        #pragma unroll
        for (int nt = 0; nt < 4; nt++) {
            int d = nt*8 + 2*tig;
            float* base = out + (size_t)(b*CC + h*32)*NN + q0;
            base[(d    )*NN + r0    ] += o[st][nt][0] * inv0;
            base[(d + 1)*NN + r0    ] += o[st][nt][1] * inv0;
            base[(d    )*NN + r0 + 8] += o[st][nt][2] * inv1;
            base[(d + 1)*NN + r0 + 8] += o[st][nt][3] * inv1;
        }
    }
}

extern "C" void kernel_launch(void* const* d_in, const int* in_sizes, int n_in,
                              void* d_out, int out_size)
{
    const float* pcd_up = (const float*)d_in[0];
    const float* sel    = (const float*)d_in[1];
    const float* drop   = (const float*)d_in[2];
    // d_in[3] = pcd_up_xyz, unused by the reference math
    const float* Wq     = (const float*)d_in[4];
    const float* Wk     = (const float*)d_in[5];
    const float* Wv     = (const float*)d_in[6];
    const float* Wsk    = (const float*)d_in[7];
    const void*  idxs   = d_in[8];
    const void*  idxd   = d_in[9];
    float* out = (float*)d_out;

    static bool attr_set = false;
    if (!attr_set) {
        cudaFuncSetAttribute(proj_kernel, cudaFuncAttributeMaxDynamicSharedMemorySize,
                             PSMEM);
        attr_set = true;
    }

    prep_kernel<<<(BB*CC*NN)/1024, 256>>>(sel, drop, idxs, idxd);
    proj_kernel<<<dim3(NN/64, BB), 256, PSMEM>>>(pcd_up, Wq, Wk, Wv, Wsk, out);
    flash_kernel<<<dim3(NN/256, HH, BB), 256>>>(out);
}